// round 12
// baseline (speedup 1.0000x reference)
#include <cuda_runtime.h>

// ----------------------------------------------------------------------------
// PeriodicPrimitives2D — R6/R11 schedule (2 pixels/thread, TILE=256, packed
// f32x2 phase math) + hybrid cosine: one of the 8 cos-pairs per iteration is
// evaluated as an fma-pipe degree-7 polynomial in d^2 instead of MUFU, to
// balance the MUFU (was 144cyc floor) and FMA (was 118cyc) pipes at ~130cyc.
// ----------------------------------------------------------------------------

#define MAX_G 4096
#define TILE  256
#define BLK   128     // threads per block; each thread owns 2 pixels

typedef unsigned long long u64;

// Per-gaussian packed data (written by prep kernel)
__device__ float4 dP [MAX_G];       // c, -s, s, c
__device__ float4 dQ [MAX_G];       // -ox, -oy, sx', sy'
__device__ float4 dC [MAX_G];       // col0, col1, col2, 0
__device__ float4 dFK[MAX_G * 4];   // fx_k, fy_k, cx_k, cy_k

// ---------------- f32x2 packed helpers --------------------------------------
__device__ __forceinline__ u64 pk2(float a, float b) {
    u64 r;
    asm("mov.b64 %0, {%1, %2};" : "=l"(r)
        : "r"(__float_as_uint(a)), "r"(__float_as_uint(b)));
    return r;
}
__device__ __forceinline__ void upk2(u64 v, float& a, float& b) {
    unsigned int lo, hi;
    asm("mov.b64 {%0, %1}, %2;" : "=r"(lo), "=r"(hi) : "l"(v));
    a = __uint_as_float(lo);
    b = __uint_as_float(hi);
}
__device__ __forceinline__ u64 mul2(u64 a, u64 b) {
    u64 r; asm("mul.rn.f32x2 %0, %1, %2;" : "=l"(r) : "l"(a), "l"(b)); return r;
}
__device__ __forceinline__ u64 fma2(u64 a, u64 b, u64 c) {
    u64 r; asm("fma.rn.f32x2 %0, %1, %2, %3;" : "=l"(r) : "l"(a), "l"(b), "l"(c));
    return r;
}
__device__ __forceinline__ float ex2(float x) {
    float r; asm("ex2.approx.f32 %0, %1;" : "=f"(r) : "f"(x)); return r;
}
__device__ __forceinline__ float cosap(float x) {
    float r; asm("cos.approx.f32 %0, %1;" : "=f"(r) : "f"(x)); return r;
}
__device__ __forceinline__ u64 dup2(float a) { return pk2(a, a); }

// Packed constants
#define C2v   0x4B4000004B400000ULL  //  1.5 * 2^23 (round-to-int magic)
#define NEG1v 0xBF800000BF800000ULL  // -1.0f
#define PI2v  0x40C90FDB40C90FDBULL  //  2*pi

// ---------------- prep: fold per-gaussian transcendentals, repack -----------
__global__ void prep_kernel(const float* __restrict__ colors,
                            const float* __restrict__ pos,
                            const float* __restrict__ scales,
                            const float* __restrict__ rots,
                            const float* __restrict__ coeffs,
                            const int*   __restrict__ indices,
                            int G) {
    int g = blockIdx.x * blockDim.x + threadIdx.x;
    if (g >= G) return;
    float s, c;
    sincosf(rots[g], &s, &c);
    float gx = pos[2 * g], gy = pos[2 * g + 1];
    float ox =  gx * c + gy * s;
    float oy = -gx * s + gy * c;
    // s' = e^scale * sqrt(0.5 * log2(e)) :  exp(-0.5*(t e^s)^2) = 2^(-(t s')^2)
    const float SCL = 0.84932180625508979f;
    dP[g] = make_float4(c, -s, s, c);
    dQ[g] = make_float4(-ox, -oy, expf(scales[2 * g]) * SCL,
                                  expf(scales[2 * g + 1]) * SCL);
    dC[g] = make_float4(colors[3 * g], colors[3 * g + 1], colors[3 * g + 2], 0.0f);

    const float FS = 1024.0f / 1024.0f;  // max_frequency / num_frequencies
#pragma unroll
    for (int k = 0; k < 4; k++) {
        float fx = (float)indices[(g * 4 + k) * 2 + 0] * FS;
        float fy = (float)indices[(g * 4 + k) * 2 + 1] * FS;
        float cx = coeffs[(g * 4 + k) * 2 + 0];
        float cy = coeffs[(g * 4 + k) * 2 + 1];
        dFK[g * 4 + k] = make_float4(fx, fy, cx, cy);
    }
}

// ---------------- render: 2 pixels/thread, smem tiles of gaussians ----------
__global__ __launch_bounds__(BLK)
void render_kernel(const float* __restrict__ x, float* __restrict__ out,
                   int N, int G) {
    __shared__ float4 sP [TILE];
    __shared__ float4 sQ [TILE];
    __shared__ float4 sC [TILE];
    __shared__ float4 sFK[TILE * 4];

    int tid  = threadIdx.x;
    int base = blockIdx.x * (2 * BLK);      // 256 pixels per block
    int i0   = base + 2 * tid;              // this thread: pixels i0, i0+1

    float pxa = 0.f, pya = 0.f, pxb = 0.f, pyb = 0.f;
    if (i0 + 1 < N) {
        float4 pp = reinterpret_cast<const float4*>(x)[i0 >> 1];
        pxa = pp.x; pya = pp.y; pxb = pp.z; pyb = pp.w;
    } else if (i0 < N) {
        float2 pp = reinterpret_cast<const float2*>(x)[i0];
        pxa = pp.x; pya = pp.y;
    }
    u64 Pxa = pk2(pxa, pxa), Pya = pk2(pya, pya);
    u64 Pxb = pk2(pxb, pxb), Pyb = pk2(pyb, pyb);

    // cos(2*pi*d), d in [-0.5,0.5]: Taylor in z=d^2 through z^7,
    // |err| <= 4.3e-6 on the interval (comparable to MUFU cos accuracy).
    u64 K1 = dup2(-19.7392088021787172f);
    u64 K2 = dup2( 64.9393940226682914f);
    u64 K3 = dup2(-85.4568172066937130f);
    u64 K4 = dup2( 60.2446413718766682f);
    u64 K5 = dup2(-26.4265678337432824f);
    u64 K6 = dup2(  7.9035363713184805f);
    u64 K7 = dup2( -1.7147339017972865f);
    u64 ONE = dup2(1.0f);

    float a0 = 0.f, a1 = 0.f, a2 = 0.f;
    float b0 = 0.f, b1 = 0.f, b2 = 0.f;

    const ulonglong2* pP  = reinterpret_cast<const ulonglong2*>(sP);
    const ulonglong2* pQ  = reinterpret_cast<const ulonglong2*>(sQ);
    const ulonglong2* pFK = reinterpret_cast<const ulonglong2*>(sFK);

    for (int t0 = 0; t0 < G; t0 += TILE) {
#pragma unroll
        for (int v = tid; v < TILE; v += BLK) {
            int gi = t0 + v;
            if (gi < G) {
                sP[v] = dP[gi];
                sQ[v] = dQ[gi];
                sC[v] = dC[gi];
#pragma unroll
                for (int k = 0; k < 4; k++) sFK[4 * v + k] = dFK[4 * gi + k];
            }
        }
        __syncthreads();

        int cnt = min(TILE, G - t0);
#pragma unroll 2
        for (int j = 0; j < cnt; j++) {
            ulonglong2 P = pP[j];            // (c,-s) , (s,c)
            ulonglong2 Q = pQ[j];            // (-ox,-oy) , (sx',sy')

            u64 ta = fma2(Pya, P.y, Q.x);
            ta = fma2(Pxa, P.x, ta);         // (txa, tya)
            u64 tb = fma2(Pyb, P.y, Q.x);
            tb = fma2(Pxb, P.x, tb);         // (txb, tyb)

            u64 ga = mul2(ta, Q.y);
            float gax, gay; upk2(ga, gax, gay);
            float gwa = ex2(fmaf(gax, -gax, gay * -gay));
            u64 gb = mul2(tb, Q.y);
            float gbx, gby; upk2(gb, gbx, gby);
            float gwb = ex2(fmaf(gbx, -gbx, gby * -gby));

            float wxa, wya, wxb, wyb;

            // ---- k = 0: pixel a via fma-pipe polynomial, pixel b via MUFU --
            {
                ulonglong2 FK = pFK[4 * j + 0];   // (fx,fy) , (cx,cy)
                float cx, cy; upk2(FK.y, cx, cy);

                u64 s1a = fma2(ta, FK.x, C2v);    // MAGIC + rint(t*f)  (exact)
                u64 rna = fma2(s1a, NEG1v, C2v);  // -rint(t*f)         (exact)
                u64 da  = fma2(ta, FK.x, rna);    // t*f mod 1, centered
                u64 z   = mul2(da, da);
                u64 p   = fma2(z, K7, K6);
                p = fma2(z, p, K5);
                p = fma2(z, p, K4);
                p = fma2(z, p, K3);
                p = fma2(z, p, K2);
                p = fma2(z, p, K1);
                p = fma2(z, p, ONE);              // cos(2*pi*da), packed
                float ca0, ca1; upk2(p, ca0, ca1);
                wxa = ca0 * cx;
                wya = ca1 * cy;

                u64 s1b = fma2(tb, FK.x, C2v);
                u64 rnb = fma2(s1b, NEG1v, C2v);
                u64 db  = fma2(tb, FK.x, rnb);
                u64 arb = mul2(db, PI2v);
                float xb0, xb1; upk2(arb, xb0, xb1);
                wxb = cosap(xb0) * cx;
                wyb = cosap(xb1) * cy;
            }

            // ---- k = 1..3: MUFU path for both pixels -----------------------
#pragma unroll
            for (int k = 1; k < 4; k++) {
                ulonglong2 FK = pFK[4 * j + k];   // (fx,fy) , (cx,cy)
                float cx, cy; upk2(FK.y, cx, cy);

                u64 s1a = fma2(ta, FK.x, C2v);
                u64 rna = fma2(s1a, NEG1v, C2v);
                u64 da  = fma2(ta, FK.x, rna);
                u64 ara = mul2(da, PI2v);
                float xa0, xa1; upk2(ara, xa0, xa1);
                wxa = fmaf(cosap(xa0), cx, wxa);
                wya = fmaf(cosap(xa1), cy, wya);

                u64 s1b = fma2(tb, FK.x, C2v);
                u64 rnb = fma2(s1b, NEG1v, C2v);
                u64 db  = fma2(tb, FK.x, rnb);
                u64 arb = mul2(db, PI2v);
                float xb0, xb1; upk2(arb, xb0, xb1);
                wxb = fmaf(cosap(xb0), cx, wxb);
                wyb = fmaf(cosap(xb1), cy, wyb);
            }

            float4 C = sC[j];
            float wa = gwa * wxa * wya;
            a0 = fmaf(wa, C.x, a0);
            a1 = fmaf(wa, C.y, a1);
            a2 = fmaf(wa, C.z, a2);
            float wb = gwb * wxb * wyb;
            b0 = fmaf(wb, C.x, b0);
            b1 = fmaf(wb, C.y, b1);
            b2 = fmaf(wb, C.z, b2);
        }
        __syncthreads();
    }

    if (i0 + 1 < N) {
        float2* o2 = reinterpret_cast<float2*>(out + 3 * i0);
        o2[0] = make_float2(a0, a1);
        o2[1] = make_float2(a2, b0);
        o2[2] = make_float2(b1, b2);
    } else if (i0 < N) {
        out[3 * i0 + 0] = a0;
        out[3 * i0 + 1] = a1;
        out[3 * i0 + 2] = a2;
    }
}

// ---------------- harness entry ---------------------------------------------
extern "C" void kernel_launch(void* const* d_in, const int* in_sizes, int n_in,
                              void* d_out, int out_size) {
    const float* x       = (const float*)d_in[0];  // [N,2]
    const float* colors  = (const float*)d_in[1];  // [G,3]
    const float* pos     = (const float*)d_in[2];  // [G,2]
    const float* scales  = (const float*)d_in[3];  // [G,2]
    const float* rots    = (const float*)d_in[4];  // [G,1]
    const float* coeffs  = (const float*)d_in[5];  // [G,4,2]
    const int*   indices = (const int*)  d_in[6];  // [G,4,2]

    int N = in_sizes[0] / 2;
    int G = in_sizes[1] / 3;
    if (G > MAX_G) G = MAX_G;

    (void)cudaFuncSetAttribute(render_kernel,
                               cudaFuncAttributePreferredSharedMemoryCarveout,
                               cudaSharedmemCarveoutMaxShared);

    prep_kernel<<<(G + 255) / 256, 256>>>(colors, pos, scales, rots,
                                          coeffs, indices, G);
    int pixPerBlk = 2 * BLK;
    render_kernel<<<(N + pixPerBlk - 1) / pixPerBlk, BLK>>>(x, (float*)d_out, N, G);
}

// round 13
// speedup vs baseline: 1.0607x; 1.0607x over previous
#include <cuda_runtime.h>

// ----------------------------------------------------------------------------
// PeriodicPrimitives2D — 4 pixels/thread (4 independent chains for ILP at the
// chronic ~30% occupancy), gaussians split 2-way across blocks so grid stays
// 1024 (wave smoothing). Partials in __device__ scratch, tiny combine kernel.
// Math identical to the 2441us best: packed-f32x2 exact phase reduction,
// MUFU cos/ex2.
// ----------------------------------------------------------------------------

#define MAX_G   4096
#define TILE    256
#define BLK     128     // threads per block
#define PXT     4       // pixels per thread -> 512 px per block
#define GSPLIT  2       // gaussian halves
#define MAX_N   262144

typedef unsigned long long u64;

// Per-gaussian packed data (written by prep kernel)
__device__ float4 dP [MAX_G];       // c, -s, s, c
__device__ float4 dQ [MAX_G];       // -ox, -oy, sx', sy'
__device__ float4 dC [MAX_G];       // col0, col1, col2, 0
__device__ float4 dFK[MAX_G * 4];   // fx_k, fy_k, cx_k, cy_k

// Partial outputs: [GSPLIT][N*3/4] float4
__device__ float4 dPart[GSPLIT][MAX_N * 3 / 4];

// ---------------- f32x2 packed helpers --------------------------------------
__device__ __forceinline__ u64 pk2(float a, float b) {
    u64 r;
    asm("mov.b64 %0, {%1, %2};" : "=l"(r)
        : "r"(__float_as_uint(a)), "r"(__float_as_uint(b)));
    return r;
}
__device__ __forceinline__ void upk2(u64 v, float& a, float& b) {
    unsigned int lo, hi;
    asm("mov.b64 {%0, %1}, %2;" : "=r"(lo), "=r"(hi) : "l"(v));
    a = __uint_as_float(lo);
    b = __uint_as_float(hi);
}
__device__ __forceinline__ u64 mul2(u64 a, u64 b) {
    u64 r; asm("mul.rn.f32x2 %0, %1, %2;" : "=l"(r) : "l"(a), "l"(b)); return r;
}
__device__ __forceinline__ u64 fma2(u64 a, u64 b, u64 c) {
    u64 r; asm("fma.rn.f32x2 %0, %1, %2, %3;" : "=l"(r) : "l"(a), "l"(b), "l"(c));
    return r;
}
__device__ __forceinline__ float ex2(float x) {
    float r; asm("ex2.approx.f32 %0, %1;" : "=f"(r) : "f"(x)); return r;
}
__device__ __forceinline__ float cosap(float x) {
    float r; asm("cos.approx.f32 %0, %1;" : "=f"(r) : "f"(x)); return r;
}

// Packed constants
#define C2v   0x4B4000004B400000ULL  //  1.5 * 2^23 (round-to-int magic)
#define NEG1v 0xBF800000BF800000ULL  // -1.0f
#define PI2v  0x40C90FDB40C90FDBULL  //  2*pi

// ---------------- prep: fold per-gaussian transcendentals, repack -----------
__global__ void prep_kernel(const float* __restrict__ colors,
                            const float* __restrict__ pos,
                            const float* __restrict__ scales,
                            const float* __restrict__ rots,
                            const float* __restrict__ coeffs,
                            const int*   __restrict__ indices,
                            int G) {
    int g = blockIdx.x * blockDim.x + threadIdx.x;
    if (g >= G) return;
    float s, c;
    sincosf(rots[g], &s, &c);
    float gx = pos[2 * g], gy = pos[2 * g + 1];
    float ox =  gx * c + gy * s;
    float oy = -gx * s + gy * c;
    // s' = e^scale * sqrt(0.5 * log2(e)) :  exp(-0.5*(t e^s)^2) = 2^(-(t s')^2)
    const float SCL = 0.84932180625508979f;
    dP[g] = make_float4(c, -s, s, c);
    dQ[g] = make_float4(-ox, -oy, expf(scales[2 * g]) * SCL,
                                  expf(scales[2 * g + 1]) * SCL);
    dC[g] = make_float4(colors[3 * g], colors[3 * g + 1], colors[3 * g + 2], 0.0f);

    const float FS = 1024.0f / 1024.0f;  // max_frequency / num_frequencies
#pragma unroll
    for (int k = 0; k < 4; k++) {
        float fx = (float)indices[(g * 4 + k) * 2 + 0] * FS;
        float fy = (float)indices[(g * 4 + k) * 2 + 1] * FS;
        float cx = coeffs[(g * 4 + k) * 2 + 0];
        float cy = coeffs[(g * 4 + k) * 2 + 1];
        dFK[g * 4 + k] = make_float4(fx, fy, cx, cy);
    }
}

// ---------------- render: 4 px/thread, half the gaussians per block ---------
__global__ __launch_bounds__(BLK)
void render_kernel(const float* __restrict__ x, int N, int G) {
    __shared__ float4 sP [TILE];
    __shared__ float4 sQ [TILE];
    __shared__ float4 sC [TILE];
    __shared__ float4 sFK[TILE * 4];

    int tid   = threadIdx.x;
    int split = blockIdx.x & (GSPLIT - 1);          // which gaussian half
    int grp   = blockIdx.x >> 1;                    // pixel group
    int i0    = grp * (PXT * BLK) + PXT * tid;      // first of 4 pixels

    float px[PXT], py[PXT];
    if (i0 + PXT - 1 < N) {
        float4 p01 = reinterpret_cast<const float4*>(x)[(i0 >> 1) + 0];
        float4 p23 = reinterpret_cast<const float4*>(x)[(i0 >> 1) + 1];
        px[0] = p01.x; py[0] = p01.y; px[1] = p01.z; py[1] = p01.w;
        px[2] = p23.x; py[2] = p23.y; px[3] = p23.z; py[3] = p23.w;
    } else {
#pragma unroll
        for (int q = 0; q < PXT; q++) {
            px[q] = (i0 + q < N) ? x[2 * (i0 + q)]     : 0.f;
            py[q] = (i0 + q < N) ? x[2 * (i0 + q) + 1] : 0.f;
        }
    }
    u64 Px[PXT], Py[PXT];
#pragma unroll
    for (int q = 0; q < PXT; q++) { Px[q] = pk2(px[q], px[q]); Py[q] = pk2(py[q], py[q]); }

    float acc[PXT][3];
#pragma unroll
    for (int q = 0; q < PXT; q++) { acc[q][0] = acc[q][1] = acc[q][2] = 0.f; }

    const ulonglong2* pP  = reinterpret_cast<const ulonglong2*>(sP);
    const ulonglong2* pQ  = reinterpret_cast<const ulonglong2*>(sQ);
    const ulonglong2* pFK = reinterpret_cast<const ulonglong2*>(sFK);

    int gLo = split * (G / GSPLIT);
    int gHi = (split == GSPLIT - 1) ? G : gLo + G / GSPLIT;

    for (int t0 = gLo; t0 < gHi; t0 += TILE) {
#pragma unroll
        for (int v = tid; v < TILE; v += BLK) {
            int gi = t0 + v;
            if (gi < gHi) {
                sP[v] = dP[gi];
                sQ[v] = dQ[gi];
                sC[v] = dC[gi];
#pragma unroll
                for (int k = 0; k < 4; k++) sFK[4 * v + k] = dFK[4 * gi + k];
            }
        }
        __syncthreads();

        int cnt = min(TILE, gHi - t0);
#pragma unroll 1
        for (int j = 0; j < cnt; j++) {
            ulonglong2 P = pP[j];            // (c,-s) , (s,c)
            ulonglong2 Q = pQ[j];            // (-ox,-oy) , (sx',sy')

            u64 t[PXT];
            float gw[PXT];
#pragma unroll
            for (int q = 0; q < PXT; q++) {
                u64 tq = fma2(Py[q], P.y, Q.x);
                tq = fma2(Px[q], P.x, tq);   // (tx, ty)
                t[q] = tq;
                u64 gq = mul2(tq, Q.y);
                float gx_, gy_; upk2(gq, gx_, gy_);
                gw[q] = ex2(fmaf(gx_, -gx_, gy_ * -gy_));
            }

            float wx[PXT], wy[PXT];
#pragma unroll
            for (int q = 0; q < PXT; q++) { wx[q] = 0.f; wy[q] = 0.f; }

#pragma unroll
            for (int k = 0; k < 4; k++) {
                ulonglong2 FK = pFK[4 * j + k];   // (fx,fy) , (cx,cy)
                float cx, cy; upk2(FK.y, cx, cy);
#pragma unroll
                for (int q = 0; q < PXT; q++) {
                    u64 s1 = fma2(t[q], FK.x, C2v);    // MAGIC + rint(t*f) (exact)
                    u64 rn = fma2(s1, NEG1v, C2v);     // -rint(t*f)        (exact)
                    u64 d  = fma2(t[q], FK.x, rn);     // t*f mod 1, centered
                    u64 ar = mul2(d, PI2v);
                    float x0, x1; upk2(ar, x0, x1);
                    wx[q] = fmaf(cosap(x0), cx, wx[q]);
                    wy[q] = fmaf(cosap(x1), cy, wy[q]);
                }
            }

            float4 C = sC[j];
#pragma unroll
            for (int q = 0; q < PXT; q++) {
                float w = gw[q] * wx[q] * wy[q];
                acc[q][0] = fmaf(w, C.x, acc[q][0]);
                acc[q][1] = fmaf(w, C.y, acc[q][1]);
                acc[q][2] = fmaf(w, C.z, acc[q][2]);
            }
        }
        __syncthreads();
    }

    // Write 12 contiguous floats (pixels i0..i0+3, 3 ch) as 3 float4s.
    if (i0 + PXT - 1 < N) {
        int base4 = (3 * i0) >> 2;   // 3*i0 is a multiple of 12 -> /4 exact
        dPart[split][base4 + 0] = make_float4(acc[0][0], acc[0][1], acc[0][2], acc[1][0]);
        dPart[split][base4 + 1] = make_float4(acc[1][1], acc[1][2], acc[2][0], acc[2][1]);
        dPart[split][base4 + 2] = make_float4(acc[2][2], acc[3][0], acc[3][1], acc[3][2]);
    } else {
        for (int q = 0; q < PXT; q++) {
            if (i0 + q < N) {
                float* pf = reinterpret_cast<float*>(dPart[split]);
                pf[3 * (i0 + q) + 0] = acc[q][0];
                pf[3 * (i0 + q) + 1] = acc[q][1];
                pf[3 * (i0 + q) + 2] = acc[q][2];
            }
        }
    }
}

// ---------------- combine: out = part0 + part1 -------------------------------
__global__ void combine_kernel(float* __restrict__ out, int n4) {
    int i = blockIdx.x * blockDim.x + threadIdx.x;
    if (i >= n4) return;
    float4 a = dPart[0][i];
    float4 b = dPart[1][i];
    reinterpret_cast<float4*>(out)[i] =
        make_float4(a.x + b.x, a.y + b.y, a.z + b.z, a.w + b.w);
}

// ---------------- harness entry ---------------------------------------------
extern "C" void kernel_launch(void* const* d_in, const int* in_sizes, int n_in,
                              void* d_out, int out_size) {
    const float* x       = (const float*)d_in[0];  // [N,2]
    const float* colors  = (const float*)d_in[1];  // [G,3]
    const float* pos     = (const float*)d_in[2];  // [G,2]
    const float* scales  = (const float*)d_in[3];  // [G,2]
    const float* rots    = (const float*)d_in[4];  // [G,1]
    const float* coeffs  = (const float*)d_in[5];  // [G,4,2]
    const int*   indices = (const int*)  d_in[6];  // [G,4,2]

    int N = in_sizes[0] / 2;
    int G = in_sizes[1] / 3;
    if (G > MAX_G) G = MAX_G;
    if (N > MAX_N) N = MAX_N;

    (void)cudaFuncSetAttribute(render_kernel,
                               cudaFuncAttributePreferredSharedMemoryCarveout,
                               cudaSharedmemCarveoutMaxShared);

    prep_kernel<<<(G + 255) / 256, 256>>>(colors, pos, scales, rots,
                                          coeffs, indices, G);

    int pixPerBlk = PXT * BLK;                       // 512
    int nGroups   = (N + pixPerBlk - 1) / pixPerBlk; // 512
    render_kernel<<<nGroups * GSPLIT, BLK>>>(x, N, G);

    int n4 = (N * 3) / 4;                            // N*3 divisible by 4 here
    combine_kernel<<<(n4 + 255) / 256, 256>>>((float*)d_out, n4);
}

// round 14
// speedup vs baseline: 1.1312x; 1.0665x over previous
#include <cuda_runtime.h>

// ----------------------------------------------------------------------------
// PeriodicPrimitives2D — R6 schedule (2 pixels/thread, TILE=256, packed-f32x2
// exact phase reduction, MUFU cos/ex2) + GSPLIT=2: each block handles half
// the gaussians so CTAs are half as long and grid=2048 gives ~2 waves,
// letting the B300 per-CTA runtime spread average out instead of bounding
// the kernel. Partials summed by a tiny combine kernel.
// ----------------------------------------------------------------------------

#define MAX_G   4096
#define TILE    256
#define BLK     128     // threads per block; each thread owns 2 pixels
#define GSPLIT  2
#define MAX_N   262144

typedef unsigned long long u64;

// Per-gaussian packed data (written by prep kernel)
__device__ float4 dP [MAX_G];       // c, -s, s, c
__device__ float4 dQ [MAX_G];       // -ox, -oy, sx', sy'
__device__ float4 dC [MAX_G];       // col0, col1, col2, 0
__device__ float4 dFK[MAX_G * 4];   // fx_k, fy_k, cx_k, cy_k

// Partial outputs: [GSPLIT][N*3/4] float4
__device__ float4 dPart[GSPLIT][MAX_N * 3 / 4];

// ---------------- f32x2 packed helpers --------------------------------------
__device__ __forceinline__ u64 pk2(float a, float b) {
    u64 r;
    asm("mov.b64 %0, {%1, %2};" : "=l"(r)
        : "r"(__float_as_uint(a)), "r"(__float_as_uint(b)));
    return r;
}
__device__ __forceinline__ void upk2(u64 v, float& a, float& b) {
    unsigned int lo, hi;
    asm("mov.b64 {%0, %1}, %2;" : "=r"(lo), "=r"(hi) : "l"(v));
    a = __uint_as_float(lo);
    b = __uint_as_float(hi);
}
__device__ __forceinline__ u64 mul2(u64 a, u64 b) {
    u64 r; asm("mul.rn.f32x2 %0, %1, %2;" : "=l"(r) : "l"(a), "l"(b)); return r;
}
__device__ __forceinline__ u64 fma2(u64 a, u64 b, u64 c) {
    u64 r; asm("fma.rn.f32x2 %0, %1, %2, %3;" : "=l"(r) : "l"(a), "l"(b), "l"(c));
    return r;
}
__device__ __forceinline__ float ex2(float x) {
    float r; asm("ex2.approx.f32 %0, %1;" : "=f"(r) : "f"(x)); return r;
}
__device__ __forceinline__ float cosap(float x) {
    float r; asm("cos.approx.f32 %0, %1;" : "=f"(r) : "f"(x)); return r;
}

// Packed constants
#define C2v   0x4B4000004B400000ULL  //  1.5 * 2^23 (round-to-int magic)
#define NEG1v 0xBF800000BF800000ULL  // -1.0f
#define PI2v  0x40C90FDB40C90FDBULL  //  2*pi

// ---------------- prep: fold per-gaussian transcendentals, repack -----------
__global__ void prep_kernel(const float* __restrict__ colors,
                            const float* __restrict__ pos,
                            const float* __restrict__ scales,
                            const float* __restrict__ rots,
                            const float* __restrict__ coeffs,
                            const int*   __restrict__ indices,
                            int G) {
    int g = blockIdx.x * blockDim.x + threadIdx.x;
    if (g >= G) return;
    float s, c;
    sincosf(rots[g], &s, &c);
    float gx = pos[2 * g], gy = pos[2 * g + 1];
    float ox =  gx * c + gy * s;
    float oy = -gx * s + gy * c;
    // s' = e^scale * sqrt(0.5 * log2(e)) :  exp(-0.5*(t e^s)^2) = 2^(-(t s')^2)
    const float SCL = 0.84932180625508979f;
    dP[g] = make_float4(c, -s, s, c);
    dQ[g] = make_float4(-ox, -oy, expf(scales[2 * g]) * SCL,
                                  expf(scales[2 * g + 1]) * SCL);
    dC[g] = make_float4(colors[3 * g], colors[3 * g + 1], colors[3 * g + 2], 0.0f);

    const float FS = 1024.0f / 1024.0f;  // max_frequency / num_frequencies
#pragma unroll
    for (int k = 0; k < 4; k++) {
        float fx = (float)indices[(g * 4 + k) * 2 + 0] * FS;
        float fy = (float)indices[(g * 4 + k) * 2 + 1] * FS;
        float cx = coeffs[(g * 4 + k) * 2 + 0];
        float cy = coeffs[(g * 4 + k) * 2 + 1];
        dFK[g * 4 + k] = make_float4(fx, fy, cx, cy);
    }
}

// ---------------- render: 2 px/thread, half the gaussians per block ---------
__global__ __launch_bounds__(BLK)
void render_kernel(const float* __restrict__ x, int N, int G) {
    __shared__ float4 sP [TILE];
    __shared__ float4 sQ [TILE];
    __shared__ float4 sC [TILE];
    __shared__ float4 sFK[TILE * 4];

    int tid   = threadIdx.x;
    int split = blockIdx.x & (GSPLIT - 1);     // gaussian half
    int grp   = blockIdx.x >> 1;               // pixel group
    int i0    = grp * (2 * BLK) + 2 * tid;     // this thread: pixels i0, i0+1

    float pxa = 0.f, pya = 0.f, pxb = 0.f, pyb = 0.f;
    if (i0 + 1 < N) {
        float4 pp = reinterpret_cast<const float4*>(x)[i0 >> 1];
        pxa = pp.x; pya = pp.y; pxb = pp.z; pyb = pp.w;
    } else if (i0 < N) {
        float2 pp = reinterpret_cast<const float2*>(x)[i0];
        pxa = pp.x; pya = pp.y;
    }
    u64 Pxa = pk2(pxa, pxa), Pya = pk2(pya, pya);
    u64 Pxb = pk2(pxb, pxb), Pyb = pk2(pyb, pyb);

    float a0 = 0.f, a1 = 0.f, a2 = 0.f;
    float b0 = 0.f, b1 = 0.f, b2 = 0.f;

    const ulonglong2* pP  = reinterpret_cast<const ulonglong2*>(sP);
    const ulonglong2* pQ  = reinterpret_cast<const ulonglong2*>(sQ);
    const ulonglong2* pFK = reinterpret_cast<const ulonglong2*>(sFK);

    int gLo = split * (G / GSPLIT);
    int gHi = (split == GSPLIT - 1) ? G : gLo + G / GSPLIT;

    for (int t0 = gLo; t0 < gHi; t0 += TILE) {
#pragma unroll
        for (int v = tid; v < TILE; v += BLK) {
            int gi = t0 + v;
            if (gi < gHi) {
                sP[v] = dP[gi];
                sQ[v] = dQ[gi];
                sC[v] = dC[gi];
#pragma unroll
                for (int k = 0; k < 4; k++) sFK[4 * v + k] = dFK[4 * gi + k];
            }
        }
        __syncthreads();

        int cnt = min(TILE, gHi - t0);
#pragma unroll 2
        for (int j = 0; j < cnt; j++) {
            ulonglong2 P = pP[j];            // (c,-s) , (s,c)
            ulonglong2 Q = pQ[j];            // (-ox,-oy) , (sx',sy')

            u64 ta = fma2(Pya, P.y, Q.x);
            ta = fma2(Pxa, P.x, ta);         // (txa, tya)
            u64 tb = fma2(Pyb, P.y, Q.x);
            tb = fma2(Pxb, P.x, tb);         // (txb, tyb)

            u64 ga = mul2(ta, Q.y);
            float gax, gay; upk2(ga, gax, gay);
            float gwa = ex2(fmaf(gax, -gax, gay * -gay));
            u64 gb = mul2(tb, Q.y);
            float gbx, gby; upk2(gb, gbx, gby);
            float gwb = ex2(fmaf(gbx, -gbx, gby * -gby));

            float wxa = 0.f, wya = 0.f, wxb = 0.f, wyb = 0.f;
#pragma unroll
            for (int k = 0; k < 4; k++) {
                ulonglong2 FK = pFK[4 * j + k];   // (fx,fy) , (cx,cy)
                float cx, cy; upk2(FK.y, cx, cy);

                u64 s1a = fma2(ta, FK.x, C2v);    // MAGIC + rint(t*f)  (exact)
                u64 rna = fma2(s1a, NEG1v, C2v);  // -rint(t*f)         (exact)
                u64 da  = fma2(ta, FK.x, rna);    // t*f mod 1, centered
                u64 ara = mul2(da, PI2v);
                float xa0, xa1; upk2(ara, xa0, xa1);
                wxa = fmaf(cosap(xa0), cx, wxa);
                wya = fmaf(cosap(xa1), cy, wya);

                u64 s1b = fma2(tb, FK.x, C2v);
                u64 rnb = fma2(s1b, NEG1v, C2v);
                u64 db  = fma2(tb, FK.x, rnb);
                u64 arb = mul2(db, PI2v);
                float xb0, xb1; upk2(arb, xb0, xb1);
                wxb = fmaf(cosap(xb0), cx, wxb);
                wyb = fmaf(cosap(xb1), cy, wyb);
            }

            float4 C = sC[j];
            float wa = gwa * wxa * wya;
            a0 = fmaf(wa, C.x, a0);
            a1 = fmaf(wa, C.y, a1);
            a2 = fmaf(wa, C.z, a2);
            float wb = gwb * wxb * wyb;
            b0 = fmaf(wb, C.x, b0);
            b1 = fmaf(wb, C.y, b1);
            b2 = fmaf(wb, C.z, b2);
        }
        __syncthreads();
    }

    float* pf = reinterpret_cast<float*>(dPart[split]);
    if (i0 + 1 < N) {
        float2* o2 = reinterpret_cast<float2*>(pf + 3 * i0);
        o2[0] = make_float2(a0, a1);
        o2[1] = make_float2(a2, b0);
        o2[2] = make_float2(b1, b2);
    } else if (i0 < N) {
        pf[3 * i0 + 0] = a0;
        pf[3 * i0 + 1] = a1;
        pf[3 * i0 + 2] = a2;
    }
}

// ---------------- combine: out = part0 + part1 -------------------------------
__global__ void combine_kernel(float* __restrict__ out, int n4, int nTail) {
    int i = blockIdx.x * blockDim.x + threadIdx.x;
    if (i < n4) {
        float4 a = dPart[0][i];
        float4 b = dPart[1][i];
        reinterpret_cast<float4*>(out)[i] =
            make_float4(a.x + b.x, a.y + b.y, a.z + b.z, a.w + b.w);
    } else if (i < n4 + nTail) {
        int e = 4 * n4 + (i - n4);
        out[e] = reinterpret_cast<const float*>(dPart[0])[e] +
                 reinterpret_cast<const float*>(dPart[1])[e];
    }
}

// ---------------- harness entry ---------------------------------------------
extern "C" void kernel_launch(void* const* d_in, const int* in_sizes, int n_in,
                              void* d_out, int out_size) {
    const float* x       = (const float*)d_in[0];  // [N,2]
    const float* colors  = (const float*)d_in[1];  // [G,3]
    const float* pos     = (const float*)d_in[2];  // [G,2]
    const float* scales  = (const float*)d_in[3];  // [G,2]
    const float* rots    = (const float*)d_in[4];  // [G,1]
    const float* coeffs  = (const float*)d_in[5];  // [G,4,2]
    const int*   indices = (const int*)  d_in[6];  // [G,4,2]

    int N = in_sizes[0] / 2;
    int G = in_sizes[1] / 3;
    if (G > MAX_G) G = MAX_G;
    if (N > MAX_N) N = MAX_N;

    (void)cudaFuncSetAttribute(render_kernel,
                               cudaFuncAttributePreferredSharedMemoryCarveout,
                               cudaSharedmemCarveoutMaxShared);

    prep_kernel<<<(G + 255) / 256, 256>>>(colors, pos, scales, rots,
                                          coeffs, indices, G);

    int pixPerBlk = 2 * BLK;                          // 256
    int nGroups   = (N + pixPerBlk - 1) / pixPerBlk;  // 1024
    render_kernel<<<nGroups * GSPLIT, BLK>>>(x, N, G);

    int n4    = (N * 3) / 4;
    int nTail = (N * 3) - 4 * n4;
    combine_kernel<<<(n4 + nTail + 255) / 256, 256>>>((float*)d_out, n4, nTail);
}